// round 2
// baseline (speedup 1.0000x reference)
#include <cuda_runtime.h>
#include <math.h>

#define BLOCK  128
#define NSPLIT 16
#define NMAX   8192
#define CUTOFF2 (1.5f * 1.5f)

// Deterministic scratch (no device-side allocation allowed).
__device__ float g_fpart[NSPLIT * NMAX * 3];   // per-split partial forces
__device__ float g_epart[4096];                // per-block partial energies

__global__ __launch_bounds__(BLOCK)
void pair_kernel(const float* __restrict__ pos,
                 const float* __restrict__ cell,
                 const float* __restrict__ sigm,
                 const float* __restrict__ epsm,
                 const float* __restrict__ alpm,
                 const int*   __restrict__ species,
                 int n, int nblocks_i)
{
    __shared__ float4 s_tile[BLOCK];           // frac coords + species (bitcast)
    __shared__ float  s_sig[64], s_eps[64], s_alp[64];
    __shared__ float  s_inv[9], s_cell[9];
    __shared__ float  s_red[BLOCK / 32];

    const int tid = threadIdx.x;

    if (tid < 64) {
        s_sig[tid] = sigm[tid];
        s_eps[tid] = epsm[tid];
        s_alp[tid] = alpm[tid];
    }
    if (tid < 9) s_cell[tid] = cell[tid];
    if (tid == 0) {
        // 3x3 inverse via adjugate (row-major cell).
        float c00=cell[0], c01=cell[1], c02=cell[2];
        float c10=cell[3], c11=cell[4], c12=cell[5];
        float c20=cell[6], c21=cell[7], c22=cell[8];
        float cof00 =  (c11*c22 - c12*c21);
        float cof01 = -(c10*c22 - c12*c20);
        float cof02 =  (c10*c21 - c11*c20);
        float cof10 = -(c01*c22 - c02*c21);
        float cof11 =  (c00*c22 - c02*c20);
        float cof12 = -(c00*c21 - c01*c20);
        float cof20 =  (c01*c12 - c02*c11);
        float cof21 = -(c00*c12 - c02*c10);
        float cof22 =  (c00*c11 - c01*c10);
        float det = c00*cof00 + c01*cof01 + c02*cof02;
        float id  = 1.0f / det;
        // inv[r][c] = cof[c][r] / det
        s_inv[0]=cof00*id; s_inv[1]=cof10*id; s_inv[2]=cof20*id;
        s_inv[3]=cof01*id; s_inv[4]=cof11*id; s_inv[5]=cof21*id;
        s_inv[6]=cof02*id; s_inv[7]=cof12*id; s_inv[8]=cof22*id;
    }
    __syncthreads();

    // Cell matrix in registers for the frac->cart transform.
    const float cc0=s_cell[0], cc1=s_cell[1], cc2=s_cell[2];
    const float cc3=s_cell[3], cc4=s_cell[4], cc5=s_cell[5];
    const float cc6=s_cell[6], cc7=s_cell[7], cc8=s_cell[8];
    const bool diag = (cc1==0.f && cc2==0.f && cc3==0.f &&
                       cc5==0.f && cc6==0.f && cc7==0.f);

    const int ib    = blockIdx.x;
    const int split = blockIdx.y;
    const int i     = ib * BLOCK + tid;

    float fix=0.f, fiy=0.f, fiz=0.f;
    int   si8 = 0;
    if (i < n) {
        float px = pos[3*i], py = pos[3*i+1], pz = pos[3*i+2];
        fix = px*s_inv[0] + py*s_inv[3] + pz*s_inv[6];
        fiy = px*s_inv[1] + py*s_inv[4] + pz*s_inv[7];
        fiz = px*s_inv[2] + py*s_inv[5] + pz*s_inv[8];
        si8 = species[i] * 8;
    }

    const int jchunk = (n + NSPLIT - 1) / NSPLIT;
    const int j0 = split * jchunk;
    const int j1 = min(n, j0 + jchunk);

    float fx=0.f, fy=0.f, fz=0.f, en=0.f;

    for (int jt = j0; jt < j1; jt += BLOCK) {
        __syncthreads();
        int j = jt + tid;
        if (j < j1) {
            float px = pos[3*j], py = pos[3*j+1], pz = pos[3*j+2];
            float a = px*s_inv[0] + py*s_inv[3] + pz*s_inv[6];
            float b = px*s_inv[1] + py*s_inv[4] + pz*s_inv[7];
            float c = px*s_inv[2] + py*s_inv[5] + pz*s_inv[8];
            s_tile[tid] = make_float4(a, b, c, __int_as_float(species[j]));
        }
        __syncthreads();

        const int cnt = min(BLOCK, j1 - jt);
        if (i < n) {
            #pragma unroll 4
            for (int jj = 0; jj < cnt; jj++) {
                float4 t = s_tile[jj];
                float d0 = t.x - fix; d0 -= rintf(d0);
                float d1 = t.y - fiy; d1 -= rintf(d1);
                float d2 = t.z - fiz; d2 -= rintf(d2);
                float dx, dy, dz;
                if (diag) {
                    dx = d0 * cc0; dy = d1 * cc4; dz = d2 * cc8;
                } else {
                    dx = d0*cc0 + d1*cc3 + d2*cc6;
                    dy = d0*cc1 + d1*cc4 + d2*cc7;
                    dz = d0*cc2 + d1*cc5 + d2*cc8;
                }
                float r2 = dx*dx + dy*dy + dz*dz;
                if (r2 < CUTOFF2 && (jt + jj) != i) {
                    float r   = sqrtf(r2);
                    int   idx = si8 + __float_as_int(t.w);
                    float sg  = s_sig[idx];
                    float fc  = 1.0f - r / sg;
                    if (fc > 0.0f) {
                        float ep  = s_eps[idx];
                        float al  = s_alp[idx];
                        float fa1 = powf(fc, al - 1.0f);   // f^(alpha-1)
                        en += (ep / al) * fa1 * fc;        // (eps/alpha) f^alpha
                        float coef = -(ep / sg) * fa1 / r; // e'(r)/r
                        fx += coef * dx;
                        fy += coef * dy;
                        fz += coef * dz;
                    }
                }
            }
        }
    }

    if (i < n) {
        int o = (split * NMAX + i) * 3;
        g_fpart[o + 0] = fx;
        g_fpart[o + 1] = fy;
        g_fpart[o + 2] = fz;
    }

    // Block energy reduction (deterministic).
    #pragma unroll
    for (int off = 16; off; off >>= 1)
        en += __shfl_xor_sync(0xFFFFFFFFu, en, off);
    if ((tid & 31) == 0) s_red[tid >> 5] = en;
    __syncthreads();
    if (tid == 0) {
        float s = 0.f;
        #pragma unroll
        for (int w = 0; w < BLOCK / 32; w++) s += s_red[w];
        g_epart[split * nblocks_i + ib] = s;
    }
}

__global__ void reduce_kernel(float* __restrict__ out, int n, int nepart)
{
    int t = blockIdx.x * blockDim.x + threadIdx.x;
    int total = 3 * n;
    if (t < total) {
        float s = 0.f;
        #pragma unroll
        for (int k = 0; k < NSPLIT; k++)
            s += g_fpart[k * NMAX * 3 + t];
        out[1 + t] = s;
    }
    if (blockIdx.x == 0) {
        __shared__ float sh[256];
        float e = 0.f;
        for (int k = threadIdx.x; k < nepart; k += blockDim.x)
            e += g_epart[k];
        sh[threadIdx.x] = e;
        __syncthreads();
        for (int off = 128; off; off >>= 1) {
            if (threadIdx.x < off) sh[threadIdx.x] += sh[threadIdx.x + off];
            __syncthreads();
        }
        if (threadIdx.x == 0) out[0] = 0.5f * sh[0];
    }
}

extern "C" void kernel_launch(void* const* d_in, const int* in_sizes, int n_in,
                              void* d_out, int out_size)
{
    const float* pos     = (const float*)d_in[0];
    const float* cell    = (const float*)d_in[1];
    const float* sigm    = (const float*)d_in[2];
    const float* epsm    = (const float*)d_in[3];
    const float* alpm    = (const float*)d_in[4];
    const int*   species = (const int*)  d_in[5];
    const int n = in_sizes[5];            // one species entry per atom

    const int nbi = (n + BLOCK - 1) / BLOCK;
    dim3 grid(nbi, NSPLIT);
    pair_kernel<<<grid, BLOCK>>>(pos, cell, sigm, epsm, alpm, species, n, nbi);

    int rthreads = 256;
    int rblocks  = (3 * n + rthreads - 1) / rthreads;
    reduce_kernel<<<rblocks, rthreads>>>((float*)d_out, n, nbi * NSPLIT);
}

// round 4
// speedup vs baseline: 1.1882x; 1.1882x over previous
#include <cuda_runtime.h>
#include <math.h>

#define NMAX   8192
#define NCMAX  4096          // max total cells (16^3)
#define CUTOFF  1.5f
#define CUTOFF2 (CUTOFF*CUTOFF)

struct Geom {
    float inv[9];    // inverse cell (row-major)
    float cm[9];     // cell matrix  (row-major)
    int ncx, ncy, ncz, ncell;
};

__device__ Geom  g_geom;
__device__ int   g_cid[NMAX];
__device__ float4 g_pfrac[NMAX];   // wrapped frac coords + species bits
__device__ int   g_count[NCMAX];
__device__ int   g_cursor[NCMAX];
__device__ int   g_off[NCMAX + 1];
__device__ int   g_slot[NMAX];     // sorted slot -> original atom index
__device__ float4 g_psort[NMAX];   // frac coords + species, cell-sorted
__device__ float g_ewarp[NMAX];    // per-atom energy partials

// ---------------------------------------------------------------- K0: init
__global__ void k0_init(const float* __restrict__ cell)
{
    int t = threadIdx.x;
    for (int c = t; c < NCMAX; c += blockDim.x) { g_count[c] = 0; g_cursor[c] = 0; }
    if (t == 0) {
        float c00=cell[0], c01=cell[1], c02=cell[2];
        float c10=cell[3], c11=cell[4], c12=cell[5];
        float c20=cell[6], c21=cell[7], c22=cell[8];
        float cof00 =  (c11*c22 - c12*c21);
        float cof01 = -(c10*c22 - c12*c20);
        float cof02 =  (c10*c21 - c11*c20);
        float cof10 = -(c01*c22 - c02*c21);
        float cof11 =  (c00*c22 - c02*c20);
        float cof12 = -(c00*c21 - c01*c20);
        float cof20 =  (c01*c12 - c02*c11);
        float cof21 = -(c00*c12 - c02*c10);
        float cof22 =  (c00*c11 - c01*c10);
        float det = c00*cof00 + c01*cof01 + c02*cof02;
        float id  = 1.0f / det;
        g_geom.inv[0]=cof00*id; g_geom.inv[1]=cof10*id; g_geom.inv[2]=cof20*id;
        g_geom.inv[3]=cof01*id; g_geom.inv[4]=cof11*id; g_geom.inv[5]=cof21*id;
        g_geom.inv[6]=cof02*id; g_geom.inv[7]=cof12*id; g_geom.inv[8]=cof22*id;
        #pragma unroll
        for (int k = 0; k < 9; k++) g_geom.cm[k] = cell[k];
        float lx = sqrtf(c00*c00 + c01*c01 + c02*c02);
        float ly = sqrtf(c10*c10 + c11*c11 + c12*c12);
        float lz = sqrtf(c20*c20 + c21*c21 + c22*c22);
        int ncx = max(1, min(16, (int)floorf(lx / CUTOFF)));
        int ncy = max(1, min(16, (int)floorf(ly / CUTOFF)));
        int ncz = max(1, min(16, (int)floorf(lz / CUTOFF)));
        g_geom.ncx = ncx; g_geom.ncy = ncy; g_geom.ncz = ncz;
        g_geom.ncell = ncx * ncy * ncz;
    }
}

// ---------------------------------------------------------------- K1: bin
__global__ void k1_bin(const float* __restrict__ pos,
                       const int*   __restrict__ species, int n)
{
    int i = blockIdx.x * blockDim.x + threadIdx.x;
    if (i >= n) return;
    float px = pos[3*i], py = pos[3*i+1], pz = pos[3*i+2];
    float fx = px*g_geom.inv[0] + py*g_geom.inv[3] + pz*g_geom.inv[6];
    float fy = px*g_geom.inv[1] + py*g_geom.inv[4] + pz*g_geom.inv[7];
    float fz = px*g_geom.inv[2] + py*g_geom.inv[5] + pz*g_geom.inv[8];
    fx -= floorf(fx); if (fx >= 1.0f) fx = 0.0f;
    fy -= floorf(fy); if (fy >= 1.0f) fy = 0.0f;
    fz -= floorf(fz); if (fz >= 1.0f) fz = 0.0f;
    int ncx = g_geom.ncx, ncy = g_geom.ncy, ncz = g_geom.ncz;
    int cx = min(ncx-1, (int)(fx * (float)ncx));
    int cy = min(ncy-1, (int)(fy * (float)ncy));
    int cz = min(ncz-1, (int)(fz * (float)ncz));
    int cid = (cz * ncy + cy) * ncx + cx;
    g_cid[i] = cid;
    g_pfrac[i] = make_float4(fx, fy, fz, __int_as_float(species[i]));
    atomicAdd(&g_count[cid], 1);
}

// ---------------------------------------------------------------- K2: scan
__global__ void k2_scan()
{
    __shared__ int s[1024];
    int t = threadIdx.x;
    int base = t * 4;
    int v0 = g_count[base+0], v1 = g_count[base+1];
    int v2 = g_count[base+2], v3 = g_count[base+3];
    int tot = v0 + v1 + v2 + v3;
    s[t] = tot;
    __syncthreads();
    for (int off = 1; off < 1024; off <<= 1) {
        int add = (t >= off) ? s[t - off] : 0;
        __syncthreads();
        s[t] += add;
        __syncthreads();
    }
    int excl = s[t] - tot;
    g_off[base+0] = excl;
    g_off[base+1] = excl + v0;
    g_off[base+2] = excl + v0 + v1;
    g_off[base+3] = excl + v0 + v1 + v2;
    if (t == 1023) g_off[NCMAX] = s[t];
}

// ---------------------------------------------------------------- K3: scatter
__global__ void k3_scatter(int n)
{
    int i = blockIdx.x * blockDim.x + threadIdx.x;
    if (i >= n) return;
    int cid = g_cid[i];
    int slot = g_off[cid] + atomicAdd(&g_cursor[cid], 1);
    g_slot[slot] = i;
}

// -------------------------------------------------- K4: per-cell sort + gather
__global__ void k4_sortcell()
{
    int c = blockIdx.x * blockDim.x + threadIdx.x;
    if (c >= g_geom.ncell) return;
    int s0 = g_off[c], s1 = g_off[c + 1];
    int cnt = s1 - s0;
    if (cnt > 1 && cnt <= 64) {
        int tmp[64];
        for (int k = 0; k < cnt; k++) tmp[k] = g_slot[s0 + k];
        for (int a = 1; a < cnt; a++) {          // insertion sort by atom index
            int key = tmp[a];
            int b = a - 1;
            while (b >= 0 && tmp[b] > key) { tmp[b+1] = tmp[b]; b--; }
            tmp[b+1] = key;
        }
        for (int k = 0; k < cnt; k++) g_slot[s0 + k] = tmp[k];
    }
    for (int k = s0; k < s1; k++) g_psort[k] = g_pfrac[g_slot[k]];
}

// ---------------------------------------------------------------- K5: pairs
__global__ __launch_bounds__(128)
void k5_pairs(const float* __restrict__ sigm,
              const float* __restrict__ epsm,
              const float* __restrict__ alpm,
              float* __restrict__ out, int n)
{
    __shared__ float s_sig[64], s_eps[64], s_alp[64];
    int tid = threadIdx.x;
    if (tid < 64) {
        s_sig[tid] = sigm[tid];
        s_eps[tid] = epsm[tid];
        s_alp[tid] = alpm[tid];
    }
    __syncthreads();

    int w    = (blockIdx.x * blockDim.x + tid) >> 5;   // one warp per sorted atom
    int lane = tid & 31;
    if (w >= n) return;

    const float cm0 = g_geom.cm[0], cm1 = g_geom.cm[1], cm2 = g_geom.cm[2];
    const float cm3 = g_geom.cm[3], cm4 = g_geom.cm[4], cm5 = g_geom.cm[5];
    const float cm6 = g_geom.cm[6], cm7 = g_geom.cm[7], cm8 = g_geom.cm[8];
    const int ncx = g_geom.ncx, ncy = g_geom.ncy, ncz = g_geom.ncz;

    float4 me = g_psort[w];
    int myspec8 = __float_as_int(me.w) * 8;
    int cx = min(ncx-1, (int)(me.x * (float)ncx));
    int cy = min(ncy-1, (int)(me.y * (float)ncy));
    int cz = min(ncz-1, (int)(me.z * (float)ncz));

    int ncid = -1;
    if (lane < 27) {
        int ax = cx + (lane % 3) - 1;
        int ay = cy + ((lane / 3) % 3) - 1;
        int az = cz + (lane / 9) - 1;
        ax += (ax < 0) ? ncx : 0;  ax -= (ax >= ncx) ? ncx : 0;
        ay += (ay < 0) ? ncy : 0;  ay -= (ay >= ncy) ? ncy : 0;
        az += (az < 0) ? ncz : 0;  az -= (az >= ncz) ? ncz : 0;
        ncid = (az * ncy + ay) * ncx + ax;
    }
    unsigned grp = __match_any_sync(0xFFFFFFFFu, ncid);
    bool keep = (lane < 27) && ((__ffs(grp) - 1) == lane);  // dedupe stencil

    int start = 0, end = 0;
    if (keep) { start = g_off[ncid]; end = g_off[ncid + 1]; }

    float fxa = 0.f, fya = 0.f, fza = 0.f, en = 0.f;
    for (int t = start; t < end; t++) {
        if (t == w) continue;                 // self
        float4 o = g_psort[t];
        float d0 = o.x - me.x; d0 -= rintf(d0);
        float d1 = o.y - me.y; d1 -= rintf(d1);
        float d2 = o.z - me.z; d2 -= rintf(d2);
        float dx = d0*cm0 + d1*cm3 + d2*cm6;
        float dy = d0*cm1 + d1*cm4 + d2*cm7;
        float dz = d0*cm2 + d1*cm5 + d2*cm8;
        float r2 = dx*dx + dy*dy + dz*dz;
        if (r2 < CUTOFF2) {
            float r   = sqrtf(r2);
            int   idx = myspec8 + __float_as_int(o.w);
            float sg  = s_sig[idx];
            float fc  = 1.0f - r / sg;
            if (fc > 0.0f) {
                float ep  = s_eps[idx];
                float al  = s_alp[idx];
                float fa1 = powf(fc, al - 1.0f);     // f^(alpha-1)
                en += (ep / al) * fa1 * fc;          // (eps/alpha) f^alpha
                float coef = -(ep / sg) * fa1 / r;   // e'(r)/r
                fxa += coef * dx;
                fya += coef * dy;
                fza += coef * dz;
            }
        }
    }

    __syncwarp();
    #pragma unroll
    for (int off = 16; off; off >>= 1) {        // deterministic fixed-order tree
        fxa += __shfl_xor_sync(0xFFFFFFFFu, fxa, off);
        fya += __shfl_xor_sync(0xFFFFFFFFu, fya, off);
        fza += __shfl_xor_sync(0xFFFFFFFFu, fza, off);
        en  += __shfl_xor_sync(0xFFFFFFFFu, en,  off);
    }
    if (lane == 0) {
        int orig = g_slot[w];
        out[1 + 3*orig + 0] = fxa;
        out[1 + 3*orig + 1] = fya;
        out[1 + 3*orig + 2] = fza;
        g_ewarp[w] = en;
    }
}

// ---------------------------------------------------------------- K6: energy
__global__ void k6_energy(float* __restrict__ out, int n)
{
    __shared__ float sh[1024];
    int t = threadIdx.x;
    float e = 0.f;
    for (int k = t; k < n; k += 1024) e += g_ewarp[k];   // fixed order
    sh[t] = e;
    __syncthreads();
    for (int off = 512; off; off >>= 1) {
        if (t < off) sh[t] += sh[t + off];
        __syncthreads();
    }
    if (t == 0) out[0] = 0.5f * sh[0];
}

// ---------------------------------------------------------------- launch
extern "C" void kernel_launch(void* const* d_in, const int* in_sizes, int n_in,
                              void* d_out, int out_size)
{
    const float* pos     = (const float*)d_in[0];
    const float* cell    = (const float*)d_in[1];
    const float* sigm    = (const float*)d_in[2];
    const float* epsm    = (const float*)d_in[3];
    const float* alpm    = (const float*)d_in[4];
    const int*   species = (const int*)  d_in[5];
    const int n = in_sizes[5];
    float* out = (float*)d_out;

    k0_init<<<1, 1024>>>(cell);
    k1_bin<<<(n + 127) / 128, 128>>>(pos, species, n);
    k2_scan<<<1, 1024>>>();
    k3_scatter<<<(n + 127) / 128, 128>>>(n);
    k4_sortcell<<<(NCMAX + 127) / 128, 128>>>();
    k5_pairs<<<(n * 32 + 127) / 128, 128>>>(sigm, epsm, alpm, out, n);
    k6_energy<<<1, 1024>>>(out, n);
}